// round 15
// baseline (speedup 1.0000x reference)
#include <cuda_runtime.h>
#include <cuda_bf16.h>
#include <cstdint>

#define SEQ 4096
#define TGT 1024
#define SENC 3072
#define HID 1024
#define H3 3072
#define IN_DIM 544
#define VOC 50000

// ---------------- scratch (static device memory; no allocations) -------------
__device__ float g_x[SEQ * IN_DIM];            // embeddings concat  [4096,544]
__device__ float g_gi_enc[SENC * H3];          // encoder input gates
__device__ float g_gi_dec[TGT * H3];           // decoder input gates
__device__ float g_henc[(SENC + 1) * HID];     // row0 = h0 = 0, rows 1..SENC = states
__device__ float g_hdec[(TGT + 1) * HID];
__device__ float g_attn[TGT * SENC];           // energies -> attn weights (in place)
__device__ float g_cat[TGT * 2 * HID];         // [hidden_state | context]
__device__ float g_stats[TGT];                 // per-row logsumexp
__device__ unsigned g_bar_cnt = 0;
__device__ unsigned g_bar_gen = 0;

// ---------------- embed ------------------------------------------------------
__global__ void k_embed(const int* __restrict__ loc, const int* __restrict__ tim,
                        const float* __restrict__ el, const float* __restrict__ et,
                        float* __restrict__ x) {
    int i = blockIdx.x;
    int t = threadIdx.x;                       // 128 threads
    float4* dst = (float4*)(x + (size_t)i * IN_DIM);
    const float4* sl = (const float4*)(el + (size_t)loc[i] * 512);
    dst[t] = sl[t];                            // 512 floats = 128 float4
    if (t < 8) {
        const float4* st = (const float4*)(et + (size_t)tim[i] * 32);
        dst[128 + t] = st[t];                  // 32 floats = 8 float4
    }
}

// ---------------- bf16 tensor-core GEMM --------------------------------------
// C[M,N] = A[M,K] * (transB ? B[N,K]^T : B[K,N]) + bias
// Requires: M%128==0, K%32==0. N guarded. lda=K. fp32 in, fp32 out, bf16 MMA.
#define GBM 128
#define GBN 128
#define GBK 32
#define GPAD 40

__global__ __launch_bounds__(256, 2)
void k_gemm(const float* __restrict__ A, const float* __restrict__ B,
            const float* __restrict__ bias, float* __restrict__ C,
            int M, int N, int K, int ldb, int ldc, int transB) {
    __shared__ __align__(16) __nv_bfloat16 As[GBM * GPAD];
    __shared__ __align__(16) __nv_bfloat16 Bs[GBN * GPAD];

    const int tid  = threadIdx.x;
    const int warp = tid >> 5, lane = tid & 31;
    const int wm = warp & 1;        // 2 warp-rows (M)
    const int wn = warp >> 1;       // 4 warp-cols (N)
    const int m0 = blockIdx.y * GBM;
    const int n0 = blockIdx.x * GBN;

    float acc[4][4][4];
#pragma unroll
    for (int i = 0; i < 4; i++)
#pragma unroll
        for (int j = 0; j < 4; j++)
#pragma unroll
            for (int r = 0; r < 4; r++) acc[i][j][r] = 0.f;

    const int lr = tid >> 3;        // 0..31
    const int lc = tid & 7;         // 0..7 (float4 within 32-wide k)

    for (int k0 = 0; k0 < K; k0 += GBK) {
        // A tile -> bf16 smem
#pragma unroll
        for (int i = 0; i < 4; i++) {
            int row = lr + 32 * i;
            float4 v = *(const float4*)(A + (size_t)(m0 + row) * K + k0 + 4 * lc);
            __nv_bfloat162* d = (__nv_bfloat162*)&As[row * GPAD + 4 * lc];
            d[0] = __floats2bfloat162_rn(v.x, v.y);
            d[1] = __floats2bfloat162_rn(v.z, v.w);
        }
        if (transB) {
#pragma unroll
            for (int i = 0; i < 4; i++) {
                int row = lr + 32 * i;
                int n = n0 + row;
                float4 v = make_float4(0.f, 0.f, 0.f, 0.f);
                if (n < N) v = *(const float4*)(B + (size_t)n * ldb + k0 + 4 * lc);
                __nv_bfloat162* d = (__nv_bfloat162*)&Bs[row * GPAD + 4 * lc];
                d[0] = __floats2bfloat162_rn(v.x, v.y);
                d[1] = __floats2bfloat162_rn(v.z, v.w);
            }
        } else {
            // B[K,N] -> Bs[n][k] (transpose in smem). Only used with exact N tiles.
            int kk = tid >> 3;
#pragma unroll
            for (int i = 0; i < 4; i++) {
                int n4 = lc + 8 * i;
                float4 v = *(const float4*)(B + (size_t)(k0 + kk) * ldb + n0 + 4 * n4);
                Bs[(4 * n4 + 0) * GPAD + kk] = __float2bfloat16(v.x);
                Bs[(4 * n4 + 1) * GPAD + kk] = __float2bfloat16(v.y);
                Bs[(4 * n4 + 2) * GPAD + kk] = __float2bfloat16(v.z);
                Bs[(4 * n4 + 3) * GPAD + kk] = __float2bfloat16(v.w);
            }
        }
        __syncthreads();

#pragma unroll
        for (int kk = 0; kk < 2; kk++) {
            uint32_t af[4][4], bf[4][2];
            const int r  = lane >> 2;
            const int cc = (lane & 3) * 2;
#pragma unroll
            for (int mt = 0; mt < 4; mt++) {
                int base = (wm * 64 + mt * 16 + r) * GPAD + kk * 16 + cc;
                af[mt][0] = *(const uint32_t*)&As[base];
                af[mt][1] = *(const uint32_t*)&As[base + 8 * GPAD];
                af[mt][2] = *(const uint32_t*)&As[base + 8];
                af[mt][3] = *(const uint32_t*)&As[base + 8 * GPAD + 8];
            }
#pragma unroll
            for (int nt = 0; nt < 4; nt++) {
                int col = wn * 32 + nt * 8 + r;
                int base = col * GPAD + kk * 16 + cc;
                bf[nt][0] = *(const uint32_t*)&Bs[base];
                bf[nt][1] = *(const uint32_t*)&Bs[base + 8];
            }
#pragma unroll
            for (int mt = 0; mt < 4; mt++)
#pragma unroll
                for (int nt = 0; nt < 4; nt++) {
                    asm volatile(
                        "mma.sync.aligned.m16n8k16.row.col.f32.bf16.bf16.f32 "
                        "{%0,%1,%2,%3}, {%4,%5,%6,%7}, {%8,%9}, {%0,%1,%2,%3};\n"
                        : "+f"(acc[mt][nt][0]), "+f"(acc[mt][nt][1]),
                          "+f"(acc[mt][nt][2]), "+f"(acc[mt][nt][3])
                        : "r"(af[mt][0]), "r"(af[mt][1]), "r"(af[mt][2]), "r"(af[mt][3]),
                          "r"(bf[nt][0]), "r"(bf[nt][1]));
                }
        }
        __syncthreads();
    }

    // epilogue
    const int r  = lane >> 2;
    const int cc = (lane & 3) * 2;
#pragma unroll
    for (int mt = 0; mt < 4; mt++) {
        int row = m0 + wm * 64 + mt * 16 + r;
#pragma unroll
        for (int nt = 0; nt < 4; nt++) {
            int col = n0 + wn * 32 + nt * 8 + cc;
            if (col < N) {
                float b0 = bias ? bias[col] : 0.f;
                C[(size_t)row * ldc + col]       = acc[mt][nt][0] + b0;
                C[(size_t)(row + 8) * ldc + col] = acc[mt][nt][2] + b0;
            }
            if (col + 1 < N) {
                float b1 = bias ? bias[col + 1] : 0.f;
                C[(size_t)row * ldc + col + 1]       = acc[mt][nt][1] + b1;
                C[(size_t)(row + 8) * ldc + col + 1] = acc[mt][nt][3] + b1;
            }
        }
    }
}

// ---------------- persistent GRU ---------------------------------------------
__device__ __forceinline__ void gridsync() {
    __syncthreads();
    if (threadIdx.x == 0) {
        __threadfence();
        unsigned gen = *(volatile unsigned*)&g_bar_gen;
        if (atomicAdd(&g_bar_cnt, 1u) == gridDim.x - 1) {
            atomicExch(&g_bar_cnt, 0u);
            __threadfence();
            *(volatile unsigned*)&g_bar_gen = gen + 1;
        } else {
            while (*(volatile unsigned*)&g_bar_gen == gen) __nanosleep(32);
        }
        __threadfence();
    }
    __syncthreads();
}

// grid = 128 CTAs x 256 threads. Each warp owns one hidden unit (128*8 = 1024).
// Whh slice lives in smem for the whole launch; h double-buffers through hbuf rows.
__global__ __launch_bounds__(256, 1)
void k_gru(const float* __restrict__ gi, const float* __restrict__ Whh,
           const float* __restrict__ bhh, float* __restrict__ hbuf, int steps) {
    extern __shared__ float sm[];
    float* wsm = sm;               // [8 warps][3 gates][1024]
    float* hsh = sm + 8 * 3 * HID; // [1024]
    const int tid = threadIdx.x, warp = tid >> 5, lane = tid & 31;
    const int unit = blockIdx.x * 8 + warp;

    // stage this warp's 3 weight rows into smem (rows: g*HID + unit)
#pragma unroll
    for (int g = 0; g < 3; g++) {
        const float4* src = (const float4*)(Whh + (size_t)(g * HID + unit) * HID);
        float4* dst = (float4*)(wsm + (warp * 3 + g) * HID);
#pragma unroll
        for (int i = lane; i < 256; i += 32) dst[i] = src[i];
    }
    if (tid < 8) hbuf[blockIdx.x * 8 + tid] = 0.f;   // h0 = 0 (row 0)
    gridsync();

    const float br = bhh[unit], bz = bhh[HID + unit], bn = bhh[2 * HID + unit];
    const float4* w0 = (const float4*)(wsm + (warp * 3 + 0) * HID);
    const float4* w1 = (const float4*)(wsm + (warp * 3 + 1) * HID);
    const float4* w2 = (const float4*)(wsm + (warp * 3 + 2) * HID);

    for (int t = 0; t < steps; t++) {
        ((float4*)hsh)[tid] = ((const float4*)(hbuf + (size_t)t * HID))[tid];
        __syncthreads();

        float4 hr[8];
#pragma unroll
        for (int m = 0; m < 8; m++) hr[m] = ((const float4*)hsh)[lane + 32 * m];

        float s0 = 0.f, s1 = 0.f, s2 = 0.f;
#pragma unroll
        for (int m = 0; m < 8; m++) {
            float4 a = w0[lane + 32 * m];
            s0 += a.x * hr[m].x + a.y * hr[m].y + a.z * hr[m].z + a.w * hr[m].w;
            float4 b = w1[lane + 32 * m];
            s1 += b.x * hr[m].x + b.y * hr[m].y + b.z * hr[m].z + b.w * hr[m].w;
            float4 c = w2[lane + 32 * m];
            s2 += c.x * hr[m].x + c.y * hr[m].y + c.z * hr[m].z + c.w * hr[m].w;
        }
#pragma unroll
        for (int o = 16; o; o >>= 1) {
            s0 += __shfl_xor_sync(0xffffffffu, s0, o);
            s1 += __shfl_xor_sync(0xffffffffu, s1, o);
            s2 += __shfl_xor_sync(0xffffffffu, s2, o);
        }
        if (lane == 0) {
            const float* git = gi + (size_t)t * H3;
            float r = 1.f / (1.f + __expf(-(git[unit] + s0 + br)));
            float z = 1.f / (1.f + __expf(-(git[HID + unit] + s1 + bz)));
            float n = tanhf(git[2 * HID + unit] + r * (s2 + bn));
            float hp = hsh[unit];
            hbuf[(size_t)(t + 1) * HID + unit] = (1.f - z) * n + z * hp;
        }
        gridsync();
    }
}

// ---------------- attention softmax (rows of 3072, in place) ------------------
__global__ void k_softmax_rows(float* __restrict__ e) {
    __shared__ float buf[SENC];
    __shared__ float red[256];
    const int row = blockIdx.x, tid = threadIdx.x;
    float* er = e + (size_t)row * SENC;

    float mx = -1e30f;
    for (int i = tid; i < SENC / 4; i += 256) {
        float4 v = ((const float4*)er)[i];
        ((float4*)buf)[i] = v;
        mx = fmaxf(mx, fmaxf(fmaxf(v.x, v.y), fmaxf(v.z, v.w)));
    }
    red[tid] = mx; __syncthreads();
    for (int s = 128; s; s >>= 1) { if (tid < s) red[tid] = fmaxf(red[tid], red[tid + s]); __syncthreads(); }
    mx = red[0]; __syncthreads();

    float sum = 0.f;
    for (int i = tid; i < SENC; i += 256) { float ev = __expf(buf[i] - mx); buf[i] = ev; sum += ev; }
    red[tid] = sum; __syncthreads();
    for (int s = 128; s; s >>= 1) { if (tid < s) red[tid] += red[tid + s]; __syncthreads(); }
    float inv = 1.f / red[0];

    for (int i = tid; i < SENC / 4; i += 256) {
        float4 v = ((const float4*)buf)[i];
        v.x *= inv; v.y *= inv; v.z *= inv; v.w *= inv;
        ((float4*)er)[i] = v;
    }
}

// ---------------- concat left half -------------------------------------------
__global__ void k_copy_h(const float* __restrict__ hs, float* __restrict__ cat) {
    int row = blockIdx.x;
    ((float4*)(cat + (size_t)row * 2 * HID))[threadIdx.x] =
        ((const float4*)(hs + (size_t)row * HID))[threadIdx.x];   // 256 thr * float4 = 1024
}

// ---------------- log-softmax over 50000 -------------------------------------
__global__ void k_ls_stats(const float* __restrict__ y, float* __restrict__ stats) {
    const int row = blockIdx.x, tid = threadIdx.x;
    const float4* yr = (const float4*)(y + (size_t)row * VOC);
    __shared__ float red[256];
    float mx = -1e30f;
    for (int i = tid; i < VOC / 4; i += 256) {
        float4 v = yr[i];
        mx = fmaxf(mx, fmaxf(fmaxf(v.x, v.y), fmaxf(v.z, v.w)));
    }
    red[tid] = mx; __syncthreads();
    for (int s = 128; s; s >>= 1) { if (tid < s) red[tid] = fmaxf(red[tid], red[tid + s]); __syncthreads(); }
    mx = red[0]; __syncthreads();
    float sum = 0.f;
    for (int i = tid; i < VOC / 4; i += 256) {
        float4 v = yr[i];
        sum += __expf(v.x - mx) + __expf(v.y - mx) + __expf(v.z - mx) + __expf(v.w - mx);
    }
    red[tid] = sum; __syncthreads();
    for (int s = 128; s; s >>= 1) { if (tid < s) red[tid] += red[tid + s]; __syncthreads(); }
    if (tid == 0) stats[row] = mx + logf(red[0]);
}

__global__ void k_ls_apply(float* __restrict__ y, const float* __restrict__ stats) {
    const int row = blockIdx.x;
    const float s = stats[row];
    float4* yr = (float4*)(y + (size_t)row * VOC);
    for (int i = threadIdx.x; i < VOC / 4; i += 256) {
        float4 v = yr[i];
        v.x -= s; v.y -= s; v.z -= s; v.w -= s;
        yr[i] = v;
    }
}

// ---------------- launch ------------------------------------------------------
extern "C" void kernel_launch(void* const* d_in, const int* in_sizes, int n_in,
                              void* d_out, int out_size) {
    const int*   loc     = (const int*)d_in[0];
    const int*   tim     = (const int*)d_in[1];
    const float* emb_loc = (const float*)d_in[3];
    const float* emb_tim = (const float*)d_in[4];
    const float* Wih_e   = (const float*)d_in[5];
    const float* Whh_e   = (const float*)d_in[6];
    const float* bih_e   = (const float*)d_in[7];
    const float* bhh_e   = (const float*)d_in[8];
    const float* Wih_d   = (const float*)d_in[9];
    const float* Whh_d   = (const float*)d_in[10];
    const float* bih_d   = (const float*)d_in[11];
    const float* bhh_d   = (const float*)d_in[12];
    const float* W_fc    = (const float*)d_in[13];
    const float* b_fc    = (const float*)d_in[14];
    float* out = (float*)d_out;

    float *x, *gie, *gid, *he, *hd, *attn, *cat, *stats;
    cudaGetSymbolAddress((void**)&x,     g_x);
    cudaGetSymbolAddress((void**)&gie,   g_gi_enc);
    cudaGetSymbolAddress((void**)&gid,   g_gi_dec);
    cudaGetSymbolAddress((void**)&he,    g_henc);
    cudaGetSymbolAddress((void**)&hd,    g_hdec);
    cudaGetSymbolAddress((void**)&attn,  g_attn);
    cudaGetSymbolAddress((void**)&cat,   g_cat);
    cudaGetSymbolAddress((void**)&stats, g_stats);

    // 1. embeddings
    k_embed<<<SEQ, 128>>>(loc, tim, emb_loc, emb_tim, x);

    // 2. input-gate GEMMs (gi = x @ Wih^T + bih)
    {
        dim3 g(H3 / GBN, SENC / GBM);
        k_gemm<<<g, 256>>>(x, Wih_e, bih_e, gie, SENC, H3, IN_DIM, IN_DIM, H3, 1);
    }
    {
        dim3 g(H3 / GBN, TGT / GBM);
        k_gemm<<<g, 256>>>(x + (size_t)SENC * IN_DIM, Wih_d, bih_d, gid, TGT, H3, IN_DIM, IN_DIM, H3, 1);
    }

    // 3. GRUs (persistent, smem-resident Whh)
    size_t gsm = (size_t)(8 * 3 * HID + HID) * sizeof(float);  // 100 KB
    cudaFuncSetAttribute(k_gru, cudaFuncAttributeMaxDynamicSharedMemorySize, (int)gsm);
    k_gru<<<128, 256, gsm>>>(gie, Whh_e, bhh_e, he, SENC);
    k_gru<<<128, 256, gsm>>>(gid, Whh_d, bhh_d, hd, TGT);

    // 4. attention: energies = h_dec @ h_enc^T ; softmax ; context = attn @ h_enc
    {
        dim3 g(SENC / GBN, TGT / GBM);
        k_gemm<<<g, 256>>>(hd + HID, he + HID, nullptr, attn, TGT, SENC, HID, HID, SENC, 1);
    }
    k_softmax_rows<<<TGT, 256>>>(attn);
    {
        dim3 g(HID / GBN, TGT / GBM);
        k_gemm<<<g, 256>>>(attn, he + HID, nullptr, cat + HID, TGT, HID, SENC, HID, 2 * HID, 0);
    }
    k_copy_h<<<TGT, 256>>>(hd + HID, cat);

    // 5. FC + log-softmax
    {
        dim3 g((VOC + GBN - 1) / GBN, TGT / GBM);
        k_gemm<<<g, 256>>>(cat, W_fc, b_fc, out, TGT, VOC, 2 * HID, 2 * HID, VOC, 1);
    }
    k_ls_stats<<<TGT, 256>>>(out, stats);
    k_ls_apply<<<TGT, 256>>>(out, stats);
}

// round 16
// speedup vs baseline: 1.8185x; 1.8185x over previous
#include <cuda_runtime.h>
#include <cuda_bf16.h>
#include <cstdint>

#define SEQ 4096
#define TGT 1024
#define SENC 3072
#define HID 1024
#define H3 3072
#define IN_DIM 544
#define VOC 50000

// ---------------- scratch (static device memory; no allocations) -------------
__device__ float g_x[SEQ * IN_DIM];            // embeddings concat  [4096,544]
__device__ float g_gi_enc[SENC * H3];          // encoder input gates
__device__ float g_gi_dec[TGT * H3];           // decoder input gates
__device__ float g_henc[(SENC + 1) * HID];     // row0 = h0 = 0, rows 1.. = states
__device__ float g_hdec[(TGT + 1) * HID];
__device__ float g_attn[TGT * SENC];           // energies -> attn weights (in place)
__device__ float g_cat[TGT * 2 * HID];         // [hidden_state | context]
__device__ float g_stats[TGT];                 // per-row logsumexp
__device__ unsigned g_cnt[2];                  // GRU arrival counters (enc, dec)

__global__ void k_zero_cnt() { g_cnt[0] = 0u; g_cnt[1] = 0u; }

// ---------------- embed ------------------------------------------------------
__global__ void k_embed(const int* __restrict__ loc, const int* __restrict__ tim,
                        const float* __restrict__ el, const float* __restrict__ et,
                        float* __restrict__ x) {
    int i = blockIdx.x;
    int t = threadIdx.x;                       // 128 threads
    float4* dst = (float4*)(x + (size_t)i * IN_DIM);
    const float4* sl = (const float4*)(el + (size_t)loc[i] * 512);
    dst[t] = sl[t];                            // 512 floats = 128 float4
    if (t < 8) {
        const float4* st = (const float4*)(et + (size_t)tim[i] * 32);
        dst[128 + t] = st[t];                  // 32 floats = 8 float4
    }
}

// ---------------- bf16 tensor-core GEMM --------------------------------------
// C[M,N] = A[M,K] * (transB ? B[N,K]^T : B[K,N]) + bias
// blockIdx.x -> M tile, blockIdx.y -> N tile (consecutive CTAs share B tile -> L2 reuse)
#define GBM 128
#define GBN 128
#define GBK 32
#define GPAD 40

__global__ __launch_bounds__(256, 2)
void k_gemm(const float* __restrict__ A, const float* __restrict__ B,
            const float* __restrict__ bias, float* __restrict__ C,
            int M, int N, int K, int ldb, int ldc, int transB) {
    __shared__ __align__(16) __nv_bfloat16 As[GBM * GPAD];
    __shared__ __align__(16) __nv_bfloat16 Bs[GBN * GPAD];

    const int tid  = threadIdx.x;
    const int warp = tid >> 5, lane = tid & 31;
    const int wm = warp & 1;        // 2 warp-rows (M)
    const int wn = warp >> 1;       // 4 warp-cols (N)
    const int m0 = blockIdx.x * GBM;
    const int n0 = blockIdx.y * GBN;

    float acc[4][4][4];
#pragma unroll
    for (int i = 0; i < 4; i++)
#pragma unroll
        for (int j = 0; j < 4; j++)
#pragma unroll
            for (int r = 0; r < 4; r++) acc[i][j][r] = 0.f;

    const int lr = tid >> 3;        // 0..31
    const int lc = tid & 7;         // 0..7 (float4 within 32-wide k)

    for (int k0 = 0; k0 < K; k0 += GBK) {
        // A tile -> bf16 smem
#pragma unroll
        for (int i = 0; i < 4; i++) {
            int row = lr + 32 * i;
            float4 v = *(const float4*)(A + (size_t)(m0 + row) * K + k0 + 4 * lc);
            __nv_bfloat162* d = (__nv_bfloat162*)&As[row * GPAD + 4 * lc];
            d[0] = __floats2bfloat162_rn(v.x, v.y);
            d[1] = __floats2bfloat162_rn(v.z, v.w);
        }
        if (transB) {
#pragma unroll
            for (int i = 0; i < 4; i++) {
                int row = lr + 32 * i;
                int n = n0 + row;
                float4 v = make_float4(0.f, 0.f, 0.f, 0.f);
                if (n < N) v = *(const float4*)(B + (size_t)n * ldb + k0 + 4 * lc);
                __nv_bfloat162* d = (__nv_bfloat162*)&Bs[row * GPAD + 4 * lc];
                d[0] = __floats2bfloat162_rn(v.x, v.y);
                d[1] = __floats2bfloat162_rn(v.z, v.w);
            }
        } else {
            // B[K,N] -> Bs[n][k] (transpose in smem). Only used with exact N tiles.
            int kk = tid >> 3;
#pragma unroll
            for (int i = 0; i < 4; i++) {
                int n4 = lc + 8 * i;
                float4 v = *(const float4*)(B + (size_t)(k0 + kk) * ldb + n0 + 4 * n4);
                Bs[(4 * n4 + 0) * GPAD + kk] = __float2bfloat16(v.x);
                Bs[(4 * n4 + 1) * GPAD + kk] = __float2bfloat16(v.y);
                Bs[(4 * n4 + 2) * GPAD + kk] = __float2bfloat16(v.z);
                Bs[(4 * n4 + 3) * GPAD + kk] = __float2bfloat16(v.w);
            }
        }
        __syncthreads();

#pragma unroll
        for (int kk = 0; kk < 2; kk++) {
            uint32_t af[4][4], bf[4][2];
            const int r  = lane >> 2;
            const int cc = (lane & 3) * 2;
#pragma unroll
            for (int mt = 0; mt < 4; mt++) {
                int base = (wm * 64 + mt * 16 + r) * GPAD + kk * 16 + cc;
                af[mt][0] = *(const uint32_t*)&As[base];
                af[mt][1] = *(const uint32_t*)&As[base + 8 * GPAD];
                af[mt][2] = *(const uint32_t*)&As[base + 8];
                af[mt][3] = *(const uint32_t*)&As[base + 8 * GPAD + 8];
            }
#pragma unroll
            for (int nt = 0; nt < 4; nt++) {
                int col = wn * 32 + nt * 8 + r;
                int base = col * GPAD + kk * 16 + cc;
                bf[nt][0] = *(const uint32_t*)&Bs[base];
                bf[nt][1] = *(const uint32_t*)&Bs[base + 8];
            }
#pragma unroll
            for (int mt = 0; mt < 4; mt++)
#pragma unroll
                for (int nt = 0; nt < 4; nt++) {
                    asm volatile(
                        "mma.sync.aligned.m16n8k16.row.col.f32.bf16.bf16.f32 "
                        "{%0,%1,%2,%3}, {%4,%5,%6,%7}, {%8,%9}, {%0,%1,%2,%3};\n"
                        : "+f"(acc[mt][nt][0]), "+f"(acc[mt][nt][1]),
                          "+f"(acc[mt][nt][2]), "+f"(acc[mt][nt][3])
                        : "r"(af[mt][0]), "r"(af[mt][1]), "r"(af[mt][2]), "r"(af[mt][3]),
                          "r"(bf[nt][0]), "r"(bf[nt][1]));
                }
        }
        __syncthreads();
    }

    // epilogue
    const int r  = lane >> 2;
    const int cc = (lane & 3) * 2;
#pragma unroll
    for (int mt = 0; mt < 4; mt++) {
        int row = m0 + wm * 64 + mt * 16 + r;
#pragma unroll
        for (int nt = 0; nt < 4; nt++) {
            int col = n0 + wn * 32 + nt * 8 + cc;
            if (col < N) {
                float b0 = bias ? bias[col] : 0.f;
                C[(size_t)row * ldc + col]       = acc[mt][nt][0] + b0;
                C[(size_t)(row + 8) * ldc + col] = acc[mt][nt][2] + b0;
            }
            if (col + 1 < N) {
                float b1 = bias ? bias[col + 1] : 0.f;
                C[(size_t)row * ldc + col + 1]       = acc[mt][nt][1] + b1;
                C[(size_t)(row + 8) * ldc + col + 1] = acc[mt][nt][3] + b1;
            }
        }
    }
}

// ---------------- persistent GRU ---------------------------------------------
// grid = 128 CTAs x 256 threads, 1 CTA/SM (100KB smem). Each warp owns one
// hidden unit per 8-unit CTA slice. Whh slice resident in smem. Cross-CTA sync:
// monotonic arrival counter, tight volatile spin (no nanosleep, no generation).
__global__ __launch_bounds__(256, 1)
void k_gru(const float* __restrict__ gi, const float* __restrict__ Whh,
           const float* __restrict__ bhh, float* __restrict__ hbuf, int steps,
           unsigned* __restrict__ cnt) {
    extern __shared__ float sm[];
    float* wsm = sm;               // [8 warps][3 gates][1024]
    float* hsh = sm + 8 * 3 * HID; // [1024]
    const int tid = threadIdx.x, warp = tid >> 5, lane = tid & 31;
    const int unit = blockIdx.x * 8 + warp;
    const unsigned NC = gridDim.x;

    // stage this warp's 3 weight rows into smem (rows: g*HID + unit)
#pragma unroll
    for (int g = 0; g < 3; g++) {
        const float4* src = (const float4*)(Whh + (size_t)(g * HID + unit) * HID);
        float4* dst = (float4*)(wsm + (warp * 3 + g) * HID);
#pragma unroll
        for (int i = lane; i < 256; i += 32) dst[i] = src[i];
    }
    if (tid < 8) hbuf[blockIdx.x * 8 + tid] = 0.f;   // h0 = 0 (row 0)
    __syncthreads();
    if (tid == 0) {
        __threadfence();
        atomicAdd(cnt, 1u);
        while (*(volatile unsigned*)cnt < NC) { }
    }
    __syncthreads();

    const float br = bhh[unit], bz = bhh[HID + unit], bn = bhh[2 * HID + unit];
    const float4* w0 = (const float4*)(wsm + (warp * 3 + 0) * HID);
    const float4* w1 = (const float4*)(wsm + (warp * 3 + 1) * HID);
    const float4* w2 = (const float4*)(wsm + (warp * 3 + 2) * HID);

    for (int t = 0; t < steps; t++) {
        // prefetch input gates early (independent of h, hides LDG latency)
        float gir = 0.f, giz = 0.f, gin = 0.f;
        if (lane == 0) {
            const float* git = gi + (size_t)t * H3;
            gir = __ldg(git + unit);
            giz = __ldg(git + HID + unit);
            gin = __ldg(git + 2 * HID + unit);
        }
        // broadcast h(t) into smem
        ((float4*)hsh)[tid] = ((const float4*)(hbuf + (size_t)t * HID))[tid];
        __syncthreads();

        float4 hr[8];
#pragma unroll
        for (int m = 0; m < 8; m++) hr[m] = ((const float4*)hsh)[lane + 32 * m];

        float s0 = 0.f, s1 = 0.f, s2 = 0.f;
#pragma unroll
        for (int m = 0; m < 8; m++) {
            float4 a = w0[lane + 32 * m];
            s0 += a.x * hr[m].x + a.y * hr[m].y + a.z * hr[m].z + a.w * hr[m].w;
            float4 b = w1[lane + 32 * m];
            s1 += b.x * hr[m].x + b.y * hr[m].y + b.z * hr[m].z + b.w * hr[m].w;
            float4 c = w2[lane + 32 * m];
            s2 += c.x * hr[m].x + c.y * hr[m].y + c.z * hr[m].z + c.w * hr[m].w;
        }
#pragma unroll
        for (int o = 16; o; o >>= 1) {
            s0 += __shfl_xor_sync(0xffffffffu, s0, o);
            s1 += __shfl_xor_sync(0xffffffffu, s1, o);
            s2 += __shfl_xor_sync(0xffffffffu, s2, o);
        }
        if (lane == 0) {
            float r = __fdividef(1.f, 1.f + __expf(-(gir + s0 + br)));
            float z = __fdividef(1.f, 1.f + __expf(-(giz + s1 + bz)));
            float xn = gin + r * (s2 + bn);
            float e2 = __expf(2.f * xn);
            float n = 1.f - __fdividef(2.f, e2 + 1.f);   // tanh(xn)
            float hp = hsh[unit];
            hbuf[(size_t)(t + 1) * HID + unit] = (1.f - z) * n + z * hp;
        }
        __syncthreads();                                  // hsh stable until all read
        if (t + 1 == steps) break;                        // no one consumes last barrier
        if (tid == 0) {
            __threadfence();
            atomicAdd(cnt, 1u);
            const unsigned tgt = NC * (unsigned)(t + 2);
            while (*(volatile unsigned*)cnt < tgt) { }
        }
        __syncthreads();
    }
}

// ---------------- attention softmax (rows of 3072, in place) ------------------
__global__ void k_softmax_rows(float* __restrict__ e) {
    __shared__ float buf[SENC];
    __shared__ float red[256];
    const int row = blockIdx.x, tid = threadIdx.x;
    float* er = e + (size_t)row * SENC;

    float mx = -1e30f;
    for (int i = tid; i < SENC / 4; i += 256) {
        float4 v = ((const float4*)er)[i];
        ((float4*)buf)[i] = v;
        mx = fmaxf(mx, fmaxf(fmaxf(v.x, v.y), fmaxf(v.z, v.w)));
    }
    red[tid] = mx; __syncthreads();
    for (int s = 128; s; s >>= 1) { if (tid < s) red[tid] = fmaxf(red[tid], red[tid + s]); __syncthreads(); }
    mx = red[0]; __syncthreads();

    float sum = 0.f;
    for (int i = tid; i < SENC; i += 256) { float ev = __expf(buf[i] - mx); buf[i] = ev; sum += ev; }
    red[tid] = sum; __syncthreads();
    for (int s = 128; s; s >>= 1) { if (tid < s) red[tid] += red[tid + s]; __syncthreads(); }
    float inv = __fdividef(1.f, red[0]);

    for (int i = tid; i < SENC / 4; i += 256) {
        float4 v = ((const float4*)buf)[i];
        v.x *= inv; v.y *= inv; v.z *= inv; v.w *= inv;
        ((float4*)er)[i] = v;
    }
}

// ---------------- concat left half -------------------------------------------
__global__ void k_copy_h(const float* __restrict__ hs, float* __restrict__ cat) {
    int row = blockIdx.x;
    ((float4*)(cat + (size_t)row * 2 * HID))[threadIdx.x] =
        ((const float4*)(hs + (size_t)row * HID))[threadIdx.x];   // 256 thr * float4 = 1024
}

// ---------------- log-softmax over 50000 -------------------------------------
__global__ void k_ls_stats(const float* __restrict__ y, float* __restrict__ stats) {
    const int row = blockIdx.x, tid = threadIdx.x;
    const float4* yr = (const float4*)(y + (size_t)row * VOC);
    __shared__ float red[256];
    float mx = -1e30f;
    for (int i = tid; i < VOC / 4; i += 256) {
        float4 v = yr[i];
        mx = fmaxf(mx, fmaxf(fmaxf(v.x, v.y), fmaxf(v.z, v.w)));
    }
    red[tid] = mx; __syncthreads();
    for (int s = 128; s; s >>= 1) { if (tid < s) red[tid] = fmaxf(red[tid], red[tid + s]); __syncthreads(); }
    mx = red[0]; __syncthreads();
    float sum = 0.f;
    for (int i = tid; i < VOC / 4; i += 256) {
        float4 v = yr[i];
        sum += __expf(v.x - mx) + __expf(v.y - mx) + __expf(v.z - mx) + __expf(v.w - mx);
    }
    red[tid] = sum; __syncthreads();
    for (int s = 128; s; s >>= 1) { if (tid < s) red[tid] += red[tid + s]; __syncthreads(); }
    if (tid == 0) stats[row] = mx + logf(red[0]);
}

__global__ void k_ls_apply(float* __restrict__ y, const float* __restrict__ stats) {
    const int row = blockIdx.x;
    const float s = stats[row];
    float4* yr = (float4*)(y + (size_t)row * VOC);
    for (int i = threadIdx.x; i < VOC / 4; i += 256) {
        float4 v = yr[i];
        v.x -= s; v.y -= s; v.z -= s; v.w -= s;
        yr[i] = v;
    }
}

// ---------------- launch ------------------------------------------------------
extern "C" void kernel_launch(void* const* d_in, const int* in_sizes, int n_in,
                              void* d_out, int out_size) {
    const int*   loc     = (const int*)d_in[0];
    const int*   tim     = (const int*)d_in[1];
    const float* emb_loc = (const float*)d_in[3];
    const float* emb_tim = (const float*)d_in[4];
    const float* Wih_e   = (const float*)d_in[5];
    const float* Whh_e   = (const float*)d_in[6];
    const float* bih_e   = (const float*)d_in[7];
    const float* bhh_e   = (const float*)d_in[8];
    const float* Wih_d   = (const float*)d_in[9];
    const float* Whh_d   = (const float*)d_in[10];
    const float* bih_d   = (const float*)d_in[11];
    const float* bhh_d   = (const float*)d_in[12];
    const float* W_fc    = (const float*)d_in[13];
    const float* b_fc    = (const float*)d_in[14];
    float* out = (float*)d_out;

    float *x, *gie, *gid, *he, *hd, *attn, *cat, *stats;
    unsigned* cnt;
    cudaGetSymbolAddress((void**)&x,     g_x);
    cudaGetSymbolAddress((void**)&gie,   g_gi_enc);
    cudaGetSymbolAddress((void**)&gid,   g_gi_dec);
    cudaGetSymbolAddress((void**)&he,    g_henc);
    cudaGetSymbolAddress((void**)&hd,    g_hdec);
    cudaGetSymbolAddress((void**)&attn,  g_attn);
    cudaGetSymbolAddress((void**)&cat,   g_cat);
    cudaGetSymbolAddress((void**)&stats, g_stats);
    cudaGetSymbolAddress((void**)&cnt,   g_cnt);

    // 0. reset GRU barrier counters (deterministic across graph replays)
    k_zero_cnt<<<1, 1>>>();

    // 1. embeddings
    k_embed<<<SEQ, 128>>>(loc, tim, emb_loc, emb_tim, x);

    // 2. input-gate GEMMs (gi = x @ Wih^T + bih)
    {
        dim3 g(SENC / GBM, H3 / GBN);
        k_gemm<<<g, 256>>>(x, Wih_e, bih_e, gie, SENC, H3, IN_DIM, IN_DIM, H3, 1);
    }
    {
        dim3 g(TGT / GBM, H3 / GBN);
        k_gemm<<<g, 256>>>(x + (size_t)SENC * IN_DIM, Wih_d, bih_d, gid, TGT, H3, IN_DIM, IN_DIM, H3, 1);
    }

    // 3. GRUs (persistent, smem-resident Whh)
    size_t gsm = (size_t)(8 * 3 * HID + HID) * sizeof(float);  // 100 KB
    cudaFuncSetAttribute(k_gru, cudaFuncAttributeMaxDynamicSharedMemorySize, (int)gsm);
    k_gru<<<128, 256, gsm>>>(gie, Whh_e, bhh_e, he, SENC, cnt);
    k_gru<<<128, 256, gsm>>>(gid, Whh_d, bhh_d, hd, TGT, cnt + 1);

    // 4. attention: energies = h_dec @ h_enc^T ; softmax ; context = attn @ h_enc
    {
        dim3 g(TGT / GBM, SENC / GBN);
        k_gemm<<<g, 256>>>(hd + HID, he + HID, nullptr, attn, TGT, SENC, HID, HID, SENC, 1);
    }
    k_softmax_rows<<<TGT, 256>>>(attn);
    {
        dim3 g(TGT / GBM, HID / GBN);
        k_gemm<<<g, 256>>>(attn, he + HID, nullptr, cat + HID, TGT, HID, SENC, HID, 2 * HID, 0);
    }
    k_copy_h<<<TGT, 256>>>(hd + HID, cat);

    // 5. FC + log-softmax
    {
        dim3 g(TGT / GBM, (VOC + GBN - 1) / GBN);
        k_gemm<<<g, 256>>>(cat, W_fc, b_fc, out, TGT, VOC, 2 * HID, 2 * HID, VOC, 1);
    }
    k_ls_stats<<<TGT, 256>>>(out, stats);
    k_ls_apply<<<TGT, 256>>>(out, stats);
}